// round 10
// baseline (speedup 1.0000x reference)
#include <cuda_runtime.h>

#define H 512
#define W 512
#define NPTS 12
#define NMAPS 16          // B(8) * 2 groups
#define TSAT 21.0f        // d >= TSAT -> tanh(2*sqrt(d)) == 1.0f exactly in fp32

typedef unsigned long long ull;

// ---- packed fp32 helpers ----
__device__ __forceinline__ ull f32x2_add(ull a, ull b) {
    ull r; asm("add.rn.f32x2 %0, %1, %2;" : "=l"(r) : "l"(a), "l"(b)); return r;
}
__device__ __forceinline__ ull f32x2_fma(ull a, ull b, ull c) {
    ull r; asm("fma.rn.f32x2 %0, %1, %2, %3;" : "=l"(r) : "l"(a), "l"(b), "l"(c)); return r;
}
__device__ __forceinline__ ull pack2(float lo, float hi) {
    ull r; asm("mov.b64 %0, {%1, %2};" : "=l"(r) : "f"(lo), "f"(hi)); return r;
}
__device__ __forceinline__ void unpack2(ull v, float& lo, float& hi) {
    asm("mov.b64 {%0, %1}, %2;" : "=f"(lo), "=f"(hi) : "l"(v));
}

// tanh(2*sqrt(d)) = 1 - 2/(exp(4*sqrt(d)) + 1); only called with d < TSAT.
__device__ __forceinline__ float fast_out(float d) {
    float s, t, r;
    asm("sqrt.approx.f32 %0, %1;" : "=f"(s) : "f"(d));
    float e = 5.770780163555852f * s;          // 4*log2(e)*sqrt(d)
    asm("ex2.approx.f32 %0, %1;" : "=f"(t) : "f"(e));
    float tp1 = t + 1.0f;
    asm("rcp.approx.f32 %0, %1;" : "=f"(r) : "f"(tp1));
    return fmaf(-2.0f, r, 1.0f);
}

// Per-row exact min over all 12 points for one float4 column, then tanh.
__device__ __forceinline__ float4 compute_px(
    float rf, ull cs0, ull cs1,
    const float* sp_y, const float* sp_nx, const float* sp_base)
{
    float m0 = 1.0e6f, m1 = 1.0e6f, m2 = 1.0e6f, m3 = 1.0e6f;
#pragma unroll
    for (int j = 0; j < NPTS; j++) {
        float t = (rf - sp_y[j]) * 0.2f;
        float a = fmaf(t, t, sp_base[j]);
        float nx = sp_nx[j];
        ull nxv = pack2(nx, nx);
        ull av  = pack2(a, a);
        ull dc, d;
        float d0, d1;
        dc = f32x2_add(cs0, nxv); d = f32x2_fma(dc, dc, av);
        unpack2(d, d0, d1); m0 = fminf(m0, d0); m1 = fminf(m1, d1);
        dc = f32x2_add(cs1, nxv); d = f32x2_fma(dc, dc, av);
        unpack2(d, d0, d1); m2 = fminf(m2, d0); m3 = fminf(m3, d1);
    }
    float4 v;
    v.x = (m0 < TSAT) ? fast_out(m0) : 1.0f;
    v.y = (m1 < TSAT) ? fast_out(m1) : 1.0f;
    v.z = (m2 < TSAT) ? fast_out(m2) : 1.0f;
    v.w = (m3 < TSAT) ? fast_out(m3) : 1.0f;
    return v;
}

// Block = (map, 4 rows). 2048 blocks x 256 threads, 2 float4/thread.
// Phase 1: unconditional 1.0f stores (no deps -> issue immediately).
// Phase 2 (warp 0, overlapped): coords LDG + 128-bit union coverage mask
//          via redux.sync, point data -> smem.
// Phase 3: covered threads (~3%) recompute exact values and overwrite
//          their OWN float4s (same-thread order => patch wins).
__global__ __launch_bounds__(256) void distmaps_kernel(
    const float* __restrict__ coords,   // (8, 24, 3)
    float* __restrict__ out)            // (8, 2, 512, 512)
{
    const int b   = blockIdx.x;
    const int m   = b >> 7;             // map 0..15
    const int r0  = (b & 127) * 4;      // first of 4 rows
    const int tid = threadIdx.x;

    const int ri = tid >> 7;            // 0/1
    const int c4 = tid & 127;           // float4 column
    const int rA = r0 + ri;
    const int rB = r0 + ri + 2;

    __shared__ float sp_y[NPTS];
    __shared__ float sp_nx[NPTS];       // -x * 0.2
    __shared__ float sp_base[NPTS];     // 0 valid, 1e6 invalid
    __shared__ unsigned s_mask[4];      // 128-bit union coverage over 4 rows

    // ---- Phase 1: store 1.0f immediately (the bulk of the work) ----
    const float4 one = make_float4(1.0f, 1.0f, 1.0f, 1.0f);
    float4* pA = (float4*)(out + ((size_t)m * H + rA) * W) + c4;
    float4* pB = (float4*)(out + ((size_t)m * H + rB) * W) + c4;
    *pA = one;
    *pB = one;

    // ---- Phase 2: warp 0 builds the coverage mask ----
    if (tid < 32) {
        unsigned w0 = 0, w1 = 0, w2 = 0, w3 = 0;
        if (tid < NPTS) {
            const float* q = coords + (m * NPTS + tid) * 3;
            float y = q[0];
            float x = q[1];
            bool valid = fmaxf(y, x) >= 0.0f;
            sp_y[tid]    = y;
            sp_nx[tid]   = -x * 0.2f;
            sp_base[tid] = valid ? 0.0f : 1000000.0f;
            if (valid) {
                // nearest integer row in [r0, r0+3] (convex in r)
                float rn = rintf(fminf(fmaxf(y, (float)r0), (float)(r0 + 3)));
                float dr = (rn - y) * 0.2f;
                if (dr * dr < TSAT) {
                    int fb = (((int)floorf(x) - 23) & ~3) >> 2;  // first f4 col
                    int lo = max(fb, 0);
                    int hi = min(fb + 12, 127);
                    if (lo <= hi) {
#pragma unroll
                        for (int w = 0; w < 4; w++) {
                            int l = lo - 32 * w, h = hi - 32 * w;
                            if (h >= 0 && l <= 31) {
                                l = max(l, 0); h = min(h, 31);
                                unsigned bits =
                                    ((h == 31) ? 0xFFFFFFFFu : ((1u << (h + 1)) - 1u))
                                    & ~((1u << l) - 1u);
                                if      (w == 0) w0 |= bits;
                                else if (w == 1) w1 |= bits;
                                else if (w == 2) w2 |= bits;
                                else             w3 |= bits;
                            }
                        }
                    }
                }
            }
        }
        w0 = __reduce_or_sync(0xffffffffu, w0);
        w1 = __reduce_or_sync(0xffffffffu, w1);
        w2 = __reduce_or_sync(0xffffffffu, w2);
        w3 = __reduce_or_sync(0xffffffffu, w3);
        if (tid == 0) {
            s_mask[0] = w0; s_mask[1] = w1; s_mask[2] = w2; s_mask[3] = w3;
        }
    }
    __syncthreads();

    // ---- Phase 3: covered threads overwrite with exact values ----
    if ((s_mask[c4 >> 5] >> (c4 & 31)) & 1u) {
        const int c = c4 * 4;
        ull cs0 = pack2((float)c * 0.2f,       (float)(c + 1) * 0.2f);
        ull cs1 = pack2((float)(c + 2) * 0.2f, (float)(c + 3) * 0.2f);
        *pA = compute_px((float)rA, cs0, cs1, sp_y, sp_nx, sp_base);
        *pB = compute_px((float)rB, cs0, cs1, sp_y, sp_nx, sp_base);
    }
}

extern "C" void kernel_launch(void* const* d_in, const int* in_sizes, int n_in,
                              void* d_out, int out_size)
{
    const float* coords = nullptr;
    for (int i = 0; i < n_in; i++) {
        if (in_sizes[i] == 8 * 24 * 3) { coords = (const float*)d_in[i]; break; }
    }
    if (!coords) coords = (const float*)d_in[n_in - 1];

    float* out = (float*)d_out;

    distmaps_kernel<<<NMAPS * 128, 256>>>(coords, out);
}